// round 16
// baseline (speedup 1.0000x reference)
#include <cuda_runtime.h>
#include <cuda_bf16.h>
#include <cstdint>

#define L_SEQ 512
#define D_MODEL 1024
#define N_HEADS 16

// ---------------- scratch (__device__ globals) ----------------
__device__ float g_xr[(size_t)8192 * 1024];            // x rounded to tf32
__device__ float g_wqkvT[(size_t)3072 * 1024];         // w_qkv^T tf32-rounded
__device__ float g_woutT[(size_t)1024 * 1024];         // w_out^T tf32-rounded
__device__ __nv_bfloat16 g_qkv_hi[(size_t)8192 * 3072];
__device__ __nv_bfloat16 g_qkv_lo[(size_t)8192 * 3072];
__device__ float g_attn[(size_t)8192 * 1024];          // attention out, tf32-rounded

// ---------------- PTX helpers ----------------
__device__ __forceinline__ uint32_t smem_u32(const void* p) {
    uint32_t a;
    asm("{ .reg .u64 t; cvta.to.shared.u64 t, %1; cvt.u32.u64 %0, t; }" : "=r"(a) : "l"(p));
    return a;
}
__device__ __forceinline__ float to_tf32(float v) {
    uint32_t r;
    asm("cvt.rna.tf32.f32 %0, %1;" : "=r"(r) : "r"(__float_as_uint(v)));
    return __uint_as_float(r);
}

#define CP_ASYNC16(dst, src) \
    asm volatile("cp.async.cg.shared.global [%0], [%1], 16;" :: "r"(dst), "l"(src))
#define CP_COMMIT() asm volatile("cp.async.commit_group;" ::: "memory")
#define CP_WAIT1()  asm volatile("cp.async.wait_group 1;" ::: "memory")
#define CP_WAIT0()  asm volatile("cp.async.wait_group 0;" ::: "memory")

#define LDMATRIX_X4(r, addr) \
    asm volatile("ldmatrix.sync.aligned.m8n8.x4.shared.b16 {%0,%1,%2,%3}, [%4];" \
                 : "=r"((r)[0]), "=r"((r)[1]), "=r"((r)[2]), "=r"((r)[3]) : "r"(addr))
#define LDMATRIX_X4_TRANS(r, addr) \
    asm volatile("ldmatrix.sync.aligned.m8n8.x4.trans.shared.b16 {%0,%1,%2,%3}, [%4];" \
                 : "=r"((r)[0]), "=r"((r)[1]), "=r"((r)[2]), "=r"((r)[3]) : "r"(addr))

#define MMA16816(c, a, b) \
    asm volatile("mma.sync.aligned.m16n8k16.row.col.f32.bf16.bf16.f32 " \
                 "{%0,%1,%2,%3},{%4,%5,%6,%7},{%8,%9},{%0,%1,%2,%3};" \
                 : "+f"((c)[0]), "+f"((c)[1]), "+f"((c)[2]), "+f"((c)[3]) \
                 : "r"((a)[0]), "r"((a)[1]), "r"((a)[2]), "r"((a)[3]), \
                   "r"((b)[0]), "r"((b)[1]))

#define MMA_TF32(c, a, b) \
    asm volatile("mma.sync.aligned.m16n8k8.row.col.f32.tf32.tf32.f32 " \
                 "{%0,%1,%2,%3},{%4,%5,%6,%7},{%8,%9},{%0,%1,%2,%3};" \
                 : "+f"((c)[0]), "+f"((c)[1]), "+f"((c)[2]), "+f"((c)[3]) \
                 : "r"((a)[0]), "r"((a)[1]), "r"((a)[2]), "r"((a)[3]), \
                   "r"((b)[0]), "r"((b)[1]))

__device__ __forceinline__ uint32_t pack_bf16x2(float a, float b) {
    __nv_bfloat162 t = __floats2bfloat162_rn(a, b);
    return *reinterpret_cast<uint32_t*>(&t);
}

// ---------------- prepass: tf32 rounding + weight transposes ----------------
__global__ __launch_bounds__(256) void prepass_kernel(
    const float* __restrict__ x,  float* __restrict__ xr,
    const float* __restrict__ wq, float* __restrict__ wqT,
    const float* __restrict__ wo, float* __restrict__ woT)
{
    __shared__ float t[32][33];
    const int b = blockIdx.x, tid = threadIdx.x;
    if (b < 8192) {
        size_t i = (size_t)b * 1024 + tid * 4;
        float4 v = *reinterpret_cast<const float4*>(x + i);
        v.x = to_tf32(v.x); v.y = to_tf32(v.y);
        v.z = to_tf32(v.z); v.w = to_tf32(v.w);
        *reinterpret_cast<float4*>(xr + i) = v;
    } else {
        const float* in; float* out; int R, C, bx, by;
        if (b < 11264) {
            in = wq; out = wqT; R = 1024; C = 3072;
            int bb = b - 8192; bx = bb % 96; by = bb / 96;
        } else {
            in = wo; out = woT; R = 1024; C = 1024;
            int bb = b - 11264; bx = bb % 32; by = bb / 32;
        }
        int x0 = tid & 31, y0 = tid >> 5;
        int c0 = bx * 32, r0 = by * 32;
#pragma unroll
        for (int i = 0; i < 32; i += 8)
            t[y0 + i][x0] = in[(size_t)(r0 + y0 + i) * C + c0 + x0];
        __syncthreads();
#pragma unroll
        for (int i = 0; i < 32; i += 8)
            out[(size_t)(c0 + y0 + i) * R + r0 + x0] = to_tf32(t[x0][y0 + i]);
    }
}

// ---------------- TF32 GEMM: BK=32 fp32, 3-stage, PADDED 144B rows (no XOR) ----------------
#define BM 128
#define BN 128
#define BKF 32
#define ROWF 144                        // 128B data + 16B pad: conflict-free, no swizzle
#define COMPF (128 * ROWF)              // 18432 per operand
#define STAGEF (2 * COMPF)              // 36864
#define GEMM_SMEM (3 * STAGEF)          // 110592

__global__ __launch_bounds__(256, 2) void gemm_tf32_kernel(
    const float* __restrict__ A, const float* __restrict__ Bt,
    const float* __restrict__ bias, float* __restrict__ C,
    __nv_bfloat16* __restrict__ Chi, __nv_bfloat16* __restrict__ Clo,
    int M, int N, int K)
{
    extern __shared__ char smem[];
    const uint32_t sbase = smem_u32(smem);
    const int tid = threadIdx.x, wid = tid >> 5, lane = tid & 31;
    const int bm = blockIdx.y * BM, bn = blockIdx.x * BN;
    const int warp_m = (wid >> 2) * 64, warp_n = (wid & 3) * 32;
    const int NT = K / BKF;

    float acc[4][4][4];
#pragma unroll
    for (int i = 0; i < 4; i++)
#pragma unroll
        for (int j = 0; j < 4; j++)
#pragma unroll
            for (int r = 0; r < 4; r++) acc[i][j][r] = 0.f;

    auto issue = [&](int s, int kt) {
        const uint32_t dst0 = sbase + s * STAGEF;
        const int k0 = kt * BKF;
#pragma unroll
        for (int op = 0; op < 2; op++) {
            const float* src = op ? Bt : A;
            const int rbase = op ? bn : bm;
#pragma unroll
            for (int i = 0; i < 4; i++) {
                int id = i * 256 + tid;           // 1024 16B chunks per operand
                int row = id >> 3, c = id & 7;
                const float* g = src + (size_t)(rbase + row) * K + k0 + c * 4;
                CP_ASYNC16(dst0 + op * COMPF + row * ROWF + c * 16, g);
            }
        }
    };

    const int lrow = lane & 15;          // ldmatrix row select
    const int lchk = lane >> 4;          // ldmatrix chunk-half select

    auto compute = [&](int s, int snx, int kt2, bool do_issue) {
        const uint32_t st = sbase + s * STAGEF;
        // loop-invariant bases; per-(mt/ntp, ks) offsets are compile-time immediates
        const uint32_t a_base = st + (warp_m + lrow) * ROWF + lchk * 16;
        const uint32_t b_base = st + COMPF + (warp_n + lrow) * ROWF + lchk * 16;
#pragma unroll
        for (int ks = 0; ks < 4; ks++) {
            uint32_t bf[4][2];
#pragma unroll
            for (int ntp = 0; ntp < 2; ntp++) {
                uint32_t r4[4];
                LDMATRIX_X4(r4, b_base + ntp * (16 * ROWF) + ks * 32);
                bf[2 * ntp][0]     = r4[0]; bf[2 * ntp][1]     = r4[2];
                bf[2 * ntp + 1][0] = r4[1]; bf[2 * ntp + 1][1] = r4[3];
            }
#pragma unroll
            for (int mt = 0; mt < 4; mt++) {
                uint32_t af[4];
                LDMATRIX_X4(af, a_base + mt * (16 * ROWF) + ks * 32);
#pragma unroll
                for (int nt = 0; nt < 4; nt++) MMA_TF32(acc[mt][nt], af, bf[nt]);
                if (ks == 0 && mt == 0 && do_issue) {
                    issue(snx, kt2);
                    CP_COMMIT();
                }
            }
        }
    };

    issue(0, 0); CP_COMMIT();
    issue(1, 1); CP_COMMIT();

    int s_kt = 0, s_nx = 2;
    for (int kt = 0; kt < NT; kt++) {
        if (kt == NT - 1) { CP_WAIT0(); }
        else              { CP_WAIT1(); }
        __syncthreads();
        compute(s_kt, s_nx, kt + 2, kt + 2 < NT);
        s_kt = (s_kt == 2) ? 0 : s_kt + 1;
        s_nx = (s_nx == 2) ? 0 : s_nx + 1;
    }

#pragma unroll
    for (int mt = 0; mt < 4; mt++) {
        int row0 = bm + warp_m + mt * 16 + (lane >> 2);
#pragma unroll
        for (int nt = 0; nt < 4; nt++) {
            int col = bn + warp_n + nt * 8 + 2 * (lane & 3);
            if (Chi) {
#pragma unroll
                for (int half = 0; half < 2; half++) {
                    float v0 = acc[mt][nt][2 * half];
                    float v1 = acc[mt][nt][2 * half + 1];
                    __nv_bfloat16 h0 = __float2bfloat16(v0);
                    __nv_bfloat16 h1 = __float2bfloat16(v1);
                    __nv_bfloat162 hp; hp.x = h0; hp.y = h1;
                    __nv_bfloat162 lp;
                    lp.x = __float2bfloat16(v0 - __bfloat162float(h0));
                    lp.y = __float2bfloat16(v1 - __bfloat162float(h1));
                    size_t o = (size_t)(row0 + half * 8) * N + col;
                    *reinterpret_cast<__nv_bfloat162*>(&Chi[o]) = hp;
                    *reinterpret_cast<__nv_bfloat162*>(&Clo[o]) = lp;
                }
            } else {
                float b0 = 0.f, b1 = 0.f;
                if (bias) { b0 = bias[col]; b1 = bias[col + 1]; }
                float2 v0 = make_float2(acc[mt][nt][0] + b0, acc[mt][nt][1] + b1);
                float2 v1 = make_float2(acc[mt][nt][2] + b0, acc[mt][nt][3] + b1);
                *reinterpret_cast<float2*>(&C[(size_t)row0 * N + col]) = v0;
                *reinterpret_cast<float2*>(&C[(size_t)(row0 + 8) * N + col]) = v1;
            }
        }
    }
}

// ---------------- Fused attention: MQ=128, K double-buffered (unchanged from R15) ----------------
#define AT_V    36864
#define AT_QB   73728
#define AT_REL  110592
#define ATTN_SMEM 113152

__global__ __launch_bounds__(256, 2) void attn_flash_kernel(const float* __restrict__ rel_emb)
{
    extern __shared__ char smc[];
    const uint32_t sb = smem_u32(smc);
    float* Rel2 = (float*)(smc + AT_REL);

    const int tid = threadIdx.x, wid = tid >> 5, lane = tid & 31;
    const int pair = blockIdx.y, bt = pair >> 4, h = pair & 15;
    const int q0 = blockIdx.x * 128;
    const int gr = lane >> 2, gc = lane & 3;
    const int lr = lane & 15, lk = lane >> 4;
    const int xrow = (lane & 7) + ((lane >> 4) << 3);
    const int xsel = ((lane >> 3) & 1) << 4;
    const int vrow = (lane & 7) + (((lane >> 3) & 1) << 3);
    const int vcol = ((lane >> 4) << 3) * 2;

    const __nv_bfloat16* ghi = g_qkv_hi + (size_t)bt * 512 * 3072 + h * 64;
    const __nv_bfloat16* glo = g_qkv_lo + (size_t)bt * 512 * 3072 + h * 64;

    auto issue_k = [&](int t, uint32_t dstbase) {
#pragma unroll
        for (int i = 0; i < 9; i++) {
            int c = i * 256 + tid;
            int sec = c / 1152, rem = c - sec * 1152;
            int row = rem / 9, ch = rem - row * 9;
            const __nv_bfloat16* base = sec ? glo : ghi;
            const __nv_bfloat16* src =
                base + (size_t)(t * 128 + row) * 3072 + 1024 + ch * 8;
            CP_ASYNC16(dstbase + sec * 18432 + row * 144 + ch * 16, src);
        }
    };
    auto issue_v = [&](int t) {
#pragma unroll
        for (int i = 0; i < 9; i++) {
            int c = i * 256 + tid;
            int sec = c / 1152, rem = c - sec * 1152;
            int row = rem / 9, ch = rem - row * 9;
            const __nv_bfloat16* base = sec ? glo : ghi;
            const __nv_bfloat16* src =
                base + (size_t)(t * 128 + row) * 3072 + 2048 + ch * 8;
            CP_ASYNC16(sb + AT_V + sec * 18432 + row * 144 + ch * 16, src);
        }
    };

    issue_k(0, sb); CP_COMMIT();
    issue_v(0); CP_COMMIT();

    {
        __nv_bfloat16* Qh = (__nv_bfloat16*)(smc + AT_QB);
        __nv_bfloat16* Ql = (__nv_bfloat16*)(smc + AT_QB + 18432);
        for (int idx = tid; idx < 8192; idx += 256) {
            int i = idx >> 6, d = idx & 63;
            size_t g = (size_t)(q0 + i) * 3072 + d;
            Qh[i * 72 + d] = __float2bfloat16(0.125f * __bfloat162float(ghi[g]));
            Ql[i * 72 + d] = __float2bfloat16(0.125f * __bfloat162float(glo[g]));
        }
        for (int idx = tid; idx < 639; idx += 256) {
            int d = idx + q0 - 511;
            int cl = min(max(d, -127), 127) + 127;
            Rel2[idx] = rel_emb[cl * N_HEADS + h];
        }
    }
    CP_WAIT0();
    __syncthreads();

    uint32_t qh[4][4], ql[4][4];
    {
        uint32_t qa = sb + AT_QB + (wid * 16 + lr) * 144 + lk * 16;
#pragma unroll
        for (int ks = 0; ks < 4; ks++) {
            LDMATRIX_X4(qh[ks], qa + ks * 32);
            LDMATRIX_X4(ql[ks], qa + 18432 + ks * 32);
        }
    }
    __syncthreads();

    float o[8][4];
#pragma unroll
    for (int n = 0; n < 8; n++)
#pragma unroll
        for (int r = 0; r < 4; r++) o[n][r] = 0.f;
    float sum0 = 0.f, sum1 = 0.f;

    const int gq0 = q0 + wid * 16 + gr;
    const int C0 = wid * 16 + gr + 511;

    auto pv = [&](int kc, const uint32_t* pfh, const uint32_t* pfl) {
#pragma unroll
        for (int dp = 0; dp < 4; dp++) {
            uint32_t va = sb + AT_V + (kc * 16 + vrow) * 144 + dp * 32 + vcol;
            uint32_t r4[4];
            uint32_t vh0[2], vh1[2], vl0[2], vl1[2];
            LDMATRIX_X4_TRANS(r4, va);
            vh0[0] = r4[0]; vh0[1] = r4[1]; vh1[0] = r4[2]; vh1[1] = r4[3];
            LDMATRIX_X4_TRANS(r4, va + 18432);
            vl0[0] = r4[0]; vl0[1] = r4[1]; vl1[0] = r4[2]; vl1[1] = r4[3];
            MMA16816(o[2 * dp],     pfh, vh0);
            MMA16816(o[2 * dp + 1], pfh, vh1);
            MMA16816(o[2 * dp],     pfh, vl0);
            MMA16816(o[2 * dp + 1], pfh, vl1);
            MMA16816(o[2 * dp],     pfl, vh0);
            MMA16816(o[2 * dp + 1], pfl, vh1);
        }
    };

#pragma unroll 1
    for (int t = 0; t < 4; t++) {
        const uint32_t kb = sb + ((t & 1) ? AT_QB : 0);
        if (t < 3) { issue_k(t + 1, sb + ((t & 1) ? 0 : AT_QB)); CP_COMMIT(); }

        uint32_t pfhA[4], pflA[4], pfhB[4], pflB[4];

#pragma unroll
        for (int kc = 0; kc < 8; kc++) {
            float acc[2][4];
#pragma unroll
            for (int j = 0; j < 2; j++)
#pragma unroll
                for (int r = 0; r < 4; r++) acc[j][r] = 0.f;

            uint32_t kh[2][4], kl[2][4];
            {
                uint32_t b0 = kb + (kc * 16 + xrow) * 144 + xsel;
                LDMATRIX_X4(kh[0], b0);
                LDMATRIX_X4(kl[0], b0 + 18432);
            }
#pragma unroll
            for (int ks = 0; ks < 4; ks++) {
                const int cur = ks & 1, nxt = cur ^ 1;
                if (ks < 3) {
                    uint32_t bn2 = kb + (kc * 16 + xrow) * 144 + xsel + (ks + 1) * 32;
                    LDMATRIX_X4(kh[nxt], bn2);
                    LDMATRIX_X4(kl[nxt], bn2 + 18432);
                }
                uint32_t bh0[2] = {kh[cur][0], kh[cur][1]};
                uint32_t bh1[2] = {kh[cur][2], kh[cur][3]};
                uint32_t bl0[2] = {kl[cur][0], kl[cur][1]};
                uint32_t bl1[2] = {kl[cur][2], kl[cur][3]};
                MMA16816(acc[0], qh[ks], bh0);
                MMA16816(acc[1], qh[ks], bh1);
                MMA16816(acc[0], qh[ks], bl0);
                MMA16816(acc[1], qh[ks], bl1);
                MMA16816(acc[0], ql[ks], bh0);
                MMA16816(acc[1], ql[ks], bh1);
            }

            uint32_t* pfh = (kc & 1) ? pfhB : pfhA;
            uint32_t* pfl = (kc & 1) ? pflB : pflA;
#pragma unroll
            for (int j = 0; j < 2; j++) {
                int gs = t * 128 + kc * 16 + j * 8 + 2 * gc;
                int i00 = C0 - gs;
                float e00 = __expf(acc[j][0] + Rel2[i00]);
                float e01 = __expf(acc[j][1] + Rel2[i00 - 1]);
                float e10 = __expf(acc[j][2] + Rel2[i00 + 8]);
                float e11 = __expf(acc[j][3] + Rel2[i00 + 7]);
                sum0 += e00 + e01;
                sum1 += e10 + e11;
                __nv_bfloat162 h0 = __floats2bfloat162_rn(e00, e01);
                __nv_bfloat162 h1 = __floats2bfloat162_rn(e10, e11);
                pfh[2 * j]     = *reinterpret_cast<uint32_t*>(&h0);
                pfh[2 * j + 1] = *reinterpret_cast<uint32_t*>(&h1);
                pfl[2 * j]     = pack_bf16x2(e00 - __bfloat162float(h0.x),
                                             e01 - __bfloat162float(h0.y));
                pfl[2 * j + 1] = pack_bf16x2(e10 - __bfloat162float(h1.x),
                                             e11 - __bfloat162float(h1.y));
            }

            if (kc == 1 && t > 0) {
                if (t < 3) { CP_WAIT1(); } else { CP_WAIT0(); }
                __syncthreads();
            }

            if (kc > 0) {
                if (kc & 1) pv(kc - 1, pfhA, pflA);
                else        pv(kc - 1, pfhB, pflB);
            }
        }
        pv(7, pfhB, pflB);

        __syncthreads();
        if (t < 3) {
            issue_v(t + 1); CP_COMMIT();
            CP_WAIT1();
            __syncthreads();
        }
    }

    sum0 += __shfl_xor_sync(0xffffffffu, sum0, 1);
    sum0 += __shfl_xor_sync(0xffffffffu, sum0, 2);
    sum1 += __shfl_xor_sync(0xffffffffu, sum1, 1);
    sum1 += __shfl_xor_sync(0xffffffffu, sum1, 2);
    float inv0 = 1.f / sum0, inv1 = 1.f / sum1;

    size_t row0 = (size_t)bt * 512 + gq0;
#pragma unroll
    for (int nt = 0; nt < 8; nt++) {
        int col = h * 64 + nt * 8 + 2 * gc;
        float2 a = make_float2(to_tf32(o[nt][0] * inv0), to_tf32(o[nt][1] * inv0));
        float2 b = make_float2(to_tf32(o[nt][2] * inv1), to_tf32(o[nt][3] * inv1));
        *reinterpret_cast<float2*>(&g_attn[row0 * 1024 + col]) = a;
        *reinterpret_cast<float2*>(&g_attn[(row0 + 8) * 1024 + col]) = b;
    }
}

// ---------------- launch ----------------
extern "C" void kernel_launch(void* const* d_in, const int* in_sizes, int n_in,
                              void* d_out, int out_size)
{
    const float* x       = (const float*)d_in[0];
    const float* w_qkv   = (const float*)d_in[1];
    const float* rel_emb = (const float*)d_in[2];
    const float* w_out   = (const float*)d_in[3];
    const float* b_out   = (const float*)d_in[4];
    float* out = (float*)d_out;

    float *xr, *wqT, *woT, *attn;
    __nv_bfloat16 *qh, *ql;
    cudaGetSymbolAddress((void**)&xr, g_xr);
    cudaGetSymbolAddress((void**)&wqT, g_wqkvT);
    cudaGetSymbolAddress((void**)&woT, g_woutT);
    cudaGetSymbolAddress((void**)&attn, g_attn);
    cudaGetSymbolAddress((void**)&qh, g_qkv_hi);
    cudaGetSymbolAddress((void**)&ql, g_qkv_lo);

    cudaFuncSetAttribute(attn_flash_kernel, cudaFuncAttributeMaxDynamicSharedMemorySize, ATTN_SMEM);
    cudaFuncSetAttribute(gemm_tf32_kernel, cudaFuncAttributeMaxDynamicSharedMemorySize, GEMM_SMEM);

    prepass_kernel<<<12288, 256>>>(x, xr, w_qkv, wqT, w_out, woT);

    gemm_tf32_kernel<<<dim3(3072 / BN, 8192 / BM), 256, GEMM_SMEM>>>(
        xr, wqT, nullptr, nullptr, qh, ql, 8192, 3072, 1024);

    attn_flash_kernel<<<dim3(L_SEQ / 128, 16 * N_HEADS), 256, ATTN_SMEM>>>(rel_emb);

    gemm_tf32_kernel<<<dim3(1024 / BN, 8192 / BM), 256, GEMM_SMEM>>>(
        attn, woT, b_out, out, nullptr, nullptr, 8192, 1024, 1024);
}

// round 17
// speedup vs baseline: 1.0756x; 1.0756x over previous
#include <cuda_runtime.h>
#include <cuda_bf16.h>
#include <cstdint>

#define L_SEQ 512
#define D_MODEL 1024
#define N_HEADS 16

// ---------------- scratch (__device__ globals) ----------------
__device__ float g_xr[(size_t)8192 * 1024];            // x rounded to tf32
__device__ float g_wqkvT[(size_t)3072 * 1024];         // w_qkv^T tf32-rounded
__device__ float g_woutT[(size_t)1024 * 1024];         // w_out^T tf32-rounded
__device__ __nv_bfloat16 g_qkv_hi[(size_t)8192 * 3072];
__device__ __nv_bfloat16 g_qkv_lo[(size_t)8192 * 3072];
__device__ float g_attn[(size_t)8192 * 1024];          // attention out, tf32-rounded

// ---------------- PTX helpers ----------------
__device__ __forceinline__ uint32_t smem_u32(const void* p) {
    uint32_t a;
    asm("{ .reg .u64 t; cvta.to.shared.u64 t, %1; cvt.u32.u64 %0, t; }" : "=r"(a) : "l"(p));
    return a;
}
__device__ __forceinline__ float to_tf32(float v) {
    uint32_t r;
    asm("cvt.rna.tf32.f32 %0, %1;" : "=r"(r) : "r"(__float_as_uint(v)));
    return __uint_as_float(r);
}

#define CP_ASYNC16(dst, src) \
    asm volatile("cp.async.cg.shared.global [%0], [%1], 16;" :: "r"(dst), "l"(src))
#define CP_COMMIT() asm volatile("cp.async.commit_group;" ::: "memory")
#define CP_WAIT1()  asm volatile("cp.async.wait_group 1;" ::: "memory")
#define CP_WAIT0()  asm volatile("cp.async.wait_group 0;" ::: "memory")

#define LDMATRIX_X4(r, addr) \
    asm volatile("ldmatrix.sync.aligned.m8n8.x4.shared.b16 {%0,%1,%2,%3}, [%4];" \
                 : "=r"((r)[0]), "=r"((r)[1]), "=r"((r)[2]), "=r"((r)[3]) : "r"(addr))
#define LDMATRIX_X4_TRANS(r, addr) \
    asm volatile("ldmatrix.sync.aligned.m8n8.x4.trans.shared.b16 {%0,%1,%2,%3}, [%4];" \
                 : "=r"((r)[0]), "=r"((r)[1]), "=r"((r)[2]), "=r"((r)[3]) : "r"(addr))

#define MMA16816(c, a, b) \
    asm volatile("mma.sync.aligned.m16n8k16.row.col.f32.bf16.bf16.f32 " \
                 "{%0,%1,%2,%3},{%4,%5,%6,%7},{%8,%9},{%0,%1,%2,%3};" \
                 : "+f"((c)[0]), "+f"((c)[1]), "+f"((c)[2]), "+f"((c)[3]) \
                 : "r"((a)[0]), "r"((a)[1]), "r"((a)[2]), "r"((a)[3]), \
                   "r"((b)[0]), "r"((b)[1]))

#define MMA_TF32(c, a, b) \
    asm volatile("mma.sync.aligned.m16n8k8.row.col.f32.tf32.tf32.f32 " \
                 "{%0,%1,%2,%3},{%4,%5,%6,%7},{%8,%9},{%0,%1,%2,%3};" \
                 : "+f"((c)[0]), "+f"((c)[1]), "+f"((c)[2]), "+f"((c)[3]) \
                 : "r"((a)[0]), "r"((a)[1]), "r"((a)[2]), "r"((a)[3]), \
                   "r"((b)[0]), "r"((b)[1]))

__device__ __forceinline__ uint32_t pack_bf16x2(float a, float b) {
    __nv_bfloat162 t = __floats2bfloat162_rn(a, b);
    return *reinterpret_cast<uint32_t*>(&t);
}

// ---------------- prepass: tf32 rounding + weight transposes ----------------
__global__ __launch_bounds__(256) void prepass_kernel(
    const float* __restrict__ x,  float* __restrict__ xr,
    const float* __restrict__ wq, float* __restrict__ wqT,
    const float* __restrict__ wo, float* __restrict__ woT)
{
    __shared__ float t[32][33];
    const int b = blockIdx.x, tid = threadIdx.x;
    if (b < 8192) {
        size_t i = (size_t)b * 1024 + tid * 4;
        float4 v = *reinterpret_cast<const float4*>(x + i);
        v.x = to_tf32(v.x); v.y = to_tf32(v.y);
        v.z = to_tf32(v.z); v.w = to_tf32(v.w);
        *reinterpret_cast<float4*>(xr + i) = v;
    } else {
        const float* in; float* out; int R, C, bx, by;
        if (b < 11264) {
            in = wq; out = wqT; R = 1024; C = 3072;
            int bb = b - 8192; bx = bb % 96; by = bb / 96;
        } else {
            in = wo; out = woT; R = 1024; C = 1024;
            int bb = b - 11264; bx = bb % 32; by = bb / 32;
        }
        int x0 = tid & 31, y0 = tid >> 5;
        int c0 = bx * 32, r0 = by * 32;
#pragma unroll
        for (int i = 0; i < 32; i += 8)
            t[y0 + i][x0] = in[(size_t)(r0 + y0 + i) * C + c0 + x0];
        __syncthreads();
#pragma unroll
        for (int i = 0; i < 32; i += 8)
            out[(size_t)(c0 + y0 + i) * R + r0 + x0] = to_tf32(t[x0][y0 + i]);
    }
}

// ---------------- TF32 GEMM: BK=32 fp32, 3-stage, XOR-swizzled 128B rows ----------------
// R17: XOR chunk offsets hoisted (thread-constant ccofs[ks]); addresses = base + immediates.
#define BM 128
#define BN 128
#define BKF 32
#define ROWF 128                        // bytes per fp32 row (32 fp32)
#define COMPF (128 * ROWF)              // 16384 per operand
#define STAGEF (2 * COMPF)              // 32768
#define GEMM_SMEM (3 * STAGEF)          // 98304

__global__ __launch_bounds__(256, 2) void gemm_tf32_kernel(
    const float* __restrict__ A, const float* __restrict__ Bt,
    const float* __restrict__ bias, float* __restrict__ C,
    __nv_bfloat16* __restrict__ Chi, __nv_bfloat16* __restrict__ Clo,
    int M, int N, int K)
{
    extern __shared__ char smem[];
    const uint32_t sbase = smem_u32(smem);
    const int tid = threadIdx.x, wid = tid >> 5, lane = tid & 31;
    const int bm = blockIdx.y * BM, bn = blockIdx.x * BN;
    const int warp_m = (wid >> 2) * 64, warp_n = (wid & 3) * 32;
    const int NT = K / BKF;

    float acc[4][4][4];
#pragma unroll
    for (int i = 0; i < 4; i++)
#pragma unroll
        for (int j = 0; j < 4; j++)
#pragma unroll
            for (int r = 0; r < 4; r++) acc[i][j][r] = 0.f;

    auto issue = [&](int s, int kt) {
        const uint32_t dst0 = sbase + s * STAGEF;
        const int k0 = kt * BKF;
#pragma unroll
        for (int op = 0; op < 2; op++) {
            const float* src = op ? Bt : A;
            const int rbase = op ? bn : bm;
#pragma unroll
            for (int i = 0; i < 4; i++) {
                int id = i * 256 + tid;           // 1024 16B chunks per operand
                int row = id >> 3, c = id & 7;
                uint32_t cc = (uint32_t)c ^ (row & 7);
                const float* g = src + (size_t)(rbase + row) * K + k0 + c * 4;
                CP_ASYNC16(dst0 + op * COMPF + row * ROWF + cc * 16, g);
            }
        }
    };

    const int lrow = lane & 15;          // ldmatrix row select
    const int lchk = lane >> 4;          // ldmatrix chunk-half select

    // Hoisted XOR: row&7 == lrow&7 (mt/ntp-invariant), so per-ks chunk offset is
    // thread-constant. 4 registers, computed once.
    uint32_t ccofs[4];
#pragma unroll
    for (int ks = 0; ks < 4; ks++)
        ccofs[ks] = (uint32_t)((2 * ks + lchk) ^ (lrow & 7)) * 16;
    const uint32_t a_row_off = (uint32_t)(warp_m + lrow) * ROWF;
    const uint32_t b_row_off = (uint32_t)COMPF + (uint32_t)(warp_n + lrow) * ROWF;

    auto compute = [&](int s, int snx, int kt2, bool do_issue) {
        const uint32_t a_base = sbase + s * STAGEF + a_row_off;
        const uint32_t b_base = sbase + s * STAGEF + b_row_off;
#pragma unroll
        for (int ks = 0; ks < 4; ks++) {
            uint32_t bf[4][2];
#pragma unroll
            for (int ntp = 0; ntp < 2; ntp++) {
                uint32_t r4[4];
                LDMATRIX_X4(r4, b_base + ntp * (16 * ROWF) + ccofs[ks]);
                bf[2 * ntp][0]     = r4[0]; bf[2 * ntp][1]     = r4[2];
                bf[2 * ntp + 1][0] = r4[1]; bf[2 * ntp + 1][1] = r4[3];
            }
#pragma unroll
            for (int mt = 0; mt < 4; mt++) {
                uint32_t af[4];
                LDMATRIX_X4(af, a_base + mt * (16 * ROWF) + ccofs[ks]);
#pragma unroll
                for (int nt = 0; nt < 4; nt++) MMA_TF32(acc[mt][nt], af, bf[nt]);
                if (ks == 0 && mt == 0 && do_issue) {
                    issue(snx, kt2);
                    CP_COMMIT();
                }
            }
        }
    };

    issue(0, 0); CP_COMMIT();
    issue(1, 1); CP_COMMIT();

    int s_kt = 0, s_nx = 2;
    for (int kt = 0; kt < NT; kt++) {
        if (kt == NT - 1) { CP_WAIT0(); }   // final tile: newest group IS this tile
        else              { CP_WAIT1(); }
        __syncthreads();
        compute(s_kt, s_nx, kt + 2, kt + 2 < NT);
        s_kt = (s_kt == 2) ? 0 : s_kt + 1;
        s_nx = (s_nx == 2) ? 0 : s_nx + 1;
    }

#pragma unroll
    for (int mt = 0; mt < 4; mt++) {
        int row0 = bm + warp_m + mt * 16 + (lane >> 2);
#pragma unroll
        for (int nt = 0; nt < 4; nt++) {
            int col = bn + warp_n + nt * 8 + 2 * (lane & 3);
            if (Chi) {
#pragma unroll
                for (int half = 0; half < 2; half++) {
                    float v0 = acc[mt][nt][2 * half];
                    float v1 = acc[mt][nt][2 * half + 1];
                    __nv_bfloat16 h0 = __float2bfloat16(v0);
                    __nv_bfloat16 h1 = __float2bfloat16(v1);
                    __nv_bfloat162 hp; hp.x = h0; hp.y = h1;
                    __nv_bfloat162 lp;
                    lp.x = __float2bfloat16(v0 - __bfloat162float(h0));
                    lp.y = __float2bfloat16(v1 - __bfloat162float(h1));
                    size_t o = (size_t)(row0 + half * 8) * N + col;
                    *reinterpret_cast<__nv_bfloat162*>(&Chi[o]) = hp;
                    *reinterpret_cast<__nv_bfloat162*>(&Clo[o]) = lp;
                }
            } else {
                float b0 = 0.f, b1 = 0.f;
                if (bias) { b0 = bias[col]; b1 = bias[col + 1]; }
                float2 v0 = make_float2(acc[mt][nt][0] + b0, acc[mt][nt][1] + b1);
                float2 v1 = make_float2(acc[mt][nt][2] + b0, acc[mt][nt][3] + b1);
                *reinterpret_cast<float2*>(&C[(size_t)row0 * N + col]) = v0;
                *reinterpret_cast<float2*>(&C[(size_t)(row0 + 8) * N + col]) = v1;
            }
        }
    }
}

// ---------------- Fused attention: MQ=128, K double-buffered (unchanged) ----------------
#define AT_V    36864
#define AT_QB   73728
#define AT_REL  110592
#define ATTN_SMEM 113152

__global__ __launch_bounds__(256, 2) void attn_flash_kernel(const float* __restrict__ rel_emb)
{
    extern __shared__ char smc[];
    const uint32_t sb = smem_u32(smc);
    float* Rel2 = (float*)(smc + AT_REL);

    const int tid = threadIdx.x, wid = tid >> 5, lane = tid & 31;
    const int pair = blockIdx.y, bt = pair >> 4, h = pair & 15;
    const int q0 = blockIdx.x * 128;
    const int gr = lane >> 2, gc = lane & 3;
    const int lr = lane & 15, lk = lane >> 4;
    const int xrow = (lane & 7) + ((lane >> 4) << 3);
    const int xsel = ((lane >> 3) & 1) << 4;
    const int vrow = (lane & 7) + (((lane >> 3) & 1) << 3);
    const int vcol = ((lane >> 4) << 3) * 2;

    const __nv_bfloat16* ghi = g_qkv_hi + (size_t)bt * 512 * 3072 + h * 64;
    const __nv_bfloat16* glo = g_qkv_lo + (size_t)bt * 512 * 3072 + h * 64;

    auto issue_k = [&](int t, uint32_t dstbase) {
#pragma unroll
        for (int i = 0; i < 9; i++) {
            int c = i * 256 + tid;
            int sec = c / 1152, rem = c - sec * 1152;
            int row = rem / 9, ch = rem - row * 9;
            const __nv_bfloat16* base = sec ? glo : ghi;
            const __nv_bfloat16* src =
                base + (size_t)(t * 128 + row) * 3072 + 1024 + ch * 8;
            CP_ASYNC16(dstbase + sec * 18432 + row * 144 + ch * 16, src);
        }
    };
    auto issue_v = [&](int t) {
#pragma unroll
        for (int i = 0; i < 9; i++) {
            int c = i * 256 + tid;
            int sec = c / 1152, rem = c - sec * 1152;
            int row = rem / 9, ch = rem - row * 9;
            const __nv_bfloat16* base = sec ? glo : ghi;
            const __nv_bfloat16* src =
                base + (size_t)(t * 128 + row) * 3072 + 2048 + ch * 8;
            CP_ASYNC16(sb + AT_V + sec * 18432 + row * 144 + ch * 16, src);
        }
    };

    issue_k(0, sb); CP_COMMIT();
    issue_v(0); CP_COMMIT();

    {
        __nv_bfloat16* Qh = (__nv_bfloat16*)(smc + AT_QB);
        __nv_bfloat16* Ql = (__nv_bfloat16*)(smc + AT_QB + 18432);
        for (int idx = tid; idx < 8192; idx += 256) {
            int i = idx >> 6, d = idx & 63;
            size_t g = (size_t)(q0 + i) * 3072 + d;
            Qh[i * 72 + d] = __float2bfloat16(0.125f * __bfloat162float(ghi[g]));
            Ql[i * 72 + d] = __float2bfloat16(0.125f * __bfloat162float(glo[g]));
        }
        for (int idx = tid; idx < 639; idx += 256) {
            int d = idx + q0 - 511;
            int cl = min(max(d, -127), 127) + 127;
            Rel2[idx] = rel_emb[cl * N_HEADS + h];
        }
    }
    CP_WAIT0();
    __syncthreads();

    uint32_t qh[4][4], ql[4][4];
    {
        uint32_t qa = sb + AT_QB + (wid * 16 + lr) * 144 + lk * 16;
#pragma unroll
        for (int ks = 0; ks < 4; ks++) {
            LDMATRIX_X4(qh[ks], qa + ks * 32);
            LDMATRIX_X4(ql[ks], qa + 18432 + ks * 32);
        }
    }
    __syncthreads();

    float o[8][4];
#pragma unroll
    for (int n = 0; n < 8; n++)
#pragma unroll
        for (int r = 0; r < 4; r++) o[n][r] = 0.f;
    float sum0 = 0.f, sum1 = 0.f;

    const int gq0 = q0 + wid * 16 + gr;
    const int C0 = wid * 16 + gr + 511;

    auto pv = [&](int kc, const uint32_t* pfh, const uint32_t* pfl) {
#pragma unroll
        for (int dp = 0; dp < 4; dp++) {
            uint32_t va = sb + AT_V + (kc * 16 + vrow) * 144 + dp * 32 + vcol;
            uint32_t r4[4];
            uint32_t vh0[2], vh1[2], vl0[2], vl1[2];
            LDMATRIX_X4_TRANS(r4, va);
            vh0[0] = r4[0]; vh0[1] = r4[1]; vh1[0] = r4[2]; vh1[1] = r4[3];
            LDMATRIX_X4_TRANS(r4, va + 18432);
            vl0[0] = r4[0]; vl0[1] = r4[1]; vl1[0] = r4[2]; vl1[1] = r4[3];
            MMA16816(o[2 * dp],     pfh, vh0);
            MMA16816(o[2 * dp + 1], pfh, vh1);
            MMA16816(o[2 * dp],     pfh, vl0);
            MMA16816(o[2 * dp + 1], pfh, vl1);
            MMA16816(o[2 * dp],     pfl, vh0);
            MMA16816(o[2 * dp + 1], pfl, vh1);
        }
    };

#pragma unroll 1
    for (int t = 0; t < 4; t++) {
        const uint32_t kb = sb + ((t & 1) ? AT_QB : 0);
        if (t < 3) { issue_k(t + 1, sb + ((t & 1) ? 0 : AT_QB)); CP_COMMIT(); }

        uint32_t pfhA[4], pflA[4], pfhB[4], pflB[4];

#pragma unroll
        for (int kc = 0; kc < 8; kc++) {
            float acc[2][4];
#pragma unroll
            for (int j = 0; j < 2; j++)
#pragma unroll
                for (int r = 0; r < 4; r++) acc[j][r] = 0.f;

            uint32_t kh[2][4], kl[2][4];
            {
                uint32_t b0 = kb + (kc * 16 + xrow) * 144 + xsel;
                LDMATRIX_X4(kh[0], b0);
                LDMATRIX_X4(kl[0], b0 + 18432);
            }
#pragma unroll
            for (int ks = 0; ks < 4; ks++) {
                const int cur = ks & 1, nxt = cur ^ 1;
                if (ks < 3) {
                    uint32_t bn2 = kb + (kc * 16 + xrow) * 144 + xsel + (ks + 1) * 32;
                    LDMATRIX_X4(kh[nxt], bn2);
                    LDMATRIX_X4(kl[nxt], bn2 + 18432);
                }
                uint32_t bh0[2] = {kh[cur][0], kh[cur][1]};
                uint32_t bh1[2] = {kh[cur][2], kh[cur][3]};
                uint32_t bl0[2] = {kl[cur][0], kl[cur][1]};
                uint32_t bl1[2] = {kl[cur][2], kl[cur][3]};
                MMA16816(acc[0], qh[ks], bh0);
                MMA16816(acc[1], qh[ks], bh1);
                MMA16816(acc[0], qh[ks], bl0);
                MMA16816(acc[1], qh[ks], bl1);
                MMA16816(acc[0], ql[ks], bh0);
                MMA16816(acc[1], ql[ks], bh1);
            }

            uint32_t* pfh = (kc & 1) ? pfhB : pfhA;
            uint32_t* pfl = (kc & 1) ? pflB : pflA;
#pragma unroll
            for (int j = 0; j < 2; j++) {
                int gs = t * 128 + kc * 16 + j * 8 + 2 * gc;
                int i00 = C0 - gs;
                float e00 = __expf(acc[j][0] + Rel2[i00]);
                float e01 = __expf(acc[j][1] + Rel2[i00 - 1]);
                float e10 = __expf(acc[j][2] + Rel2[i00 + 8]);
                float e11 = __expf(acc[j][3] + Rel2[i00 + 7]);
                sum0 += e00 + e01;
                sum1 += e10 + e11;
                __nv_bfloat162 h0 = __floats2bfloat162_rn(e00, e01);
                __nv_bfloat162 h1 = __floats2bfloat162_rn(e10, e11);
                pfh[2 * j]     = *reinterpret_cast<uint32_t*>(&h0);
                pfh[2 * j + 1] = *reinterpret_cast<uint32_t*>(&h1);
                pfl[2 * j]     = pack_bf16x2(e00 - __bfloat162float(h0.x),
                                             e01 - __bfloat162float(h0.y));
                pfl[2 * j + 1] = pack_bf16x2(e10 - __bfloat162float(h1.x),
                                             e11 - __bfloat162float(h1.y));
            }

            if (kc == 1 && t > 0) {
                if (t < 3) { CP_WAIT1(); } else { CP_WAIT0(); }
                __syncthreads();
            }

            if (kc > 0) {
                if (kc & 1) pv(kc - 1, pfhA, pflA);
                else        pv(kc - 1, pfhB, pflB);
            }
        }
        pv(7, pfhB, pflB);

        __syncthreads();
        if (t < 3) {
            issue_v(t + 1); CP_COMMIT();
            CP_WAIT1();
            __syncthreads();
        }
    }

    sum0 += __shfl_xor_sync(0xffffffffu, sum0, 1);
    sum0 += __shfl_xor_sync(0xffffffffu, sum0, 2);
    sum1 += __shfl_xor_sync(0xffffffffu, sum1, 1);
    sum1 += __shfl_xor_sync(0xffffffffu, sum1, 2);
    float inv0 = 1.f / sum0, inv1 = 1.f / sum1;

    size_t row0 = (size_t)bt * 512 + gq0;
#pragma unroll
    for (int nt = 0; nt < 8; nt++) {
        int col = h * 64 + nt * 8 + 2 * gc;
        float2 a = make_float2(to_tf32(o[nt][0] * inv0), to_tf32(o[nt][1] * inv0));
        float2 b = make_float2(to_tf32(o[nt][2] * inv1), to_tf32(o[nt][3] * inv1));
        *reinterpret_cast<float2*>(&g_attn[row0 * 1024 + col]) = a;
        *reinterpret_cast<float2*>(&g_attn[(row0 + 8) * 1024 + col]) = b;
    }
}

// ---------------- launch ----------------
extern "C" void kernel_launch(void* const* d_in, const int* in_sizes, int n_in,
                              void* d_out, int out_size)
{
    const float* x       = (const float*)d_in[0];
    const float* w_qkv   = (const float*)d_in[1];
    const float* rel_emb = (const float*)d_in[2];
    const float* w_out   = (const float*)d_in[3];
    const float* b_out   = (const float*)d_in[4];
    float* out = (float*)d_out;

    float *xr, *wqT, *woT, *attn;
    __nv_bfloat16 *qh, *ql;
    cudaGetSymbolAddress((void**)&xr, g_xr);
    cudaGetSymbolAddress((void**)&wqT, g_wqkvT);
    cudaGetSymbolAddress((void**)&woT, g_woutT);
    cudaGetSymbolAddress((void**)&attn, g_attn);
    cudaGetSymbolAddress((void**)&qh, g_qkv_hi);
    cudaGetSymbolAddress((void**)&ql, g_qkv_lo);

    cudaFuncSetAttribute(attn_flash_kernel, cudaFuncAttributeMaxDynamicSharedMemorySize, ATTN_SMEM);
    cudaFuncSetAttribute(gemm_tf32_kernel, cudaFuncAttributeMaxDynamicSharedMemorySize, GEMM_SMEM);

    prepass_kernel<<<12288, 256>>>(x, xr, w_qkv, wqT, w_out, woT);

    gemm_tf32_kernel<<<dim3(3072 / BN, 8192 / BM), 256, GEMM_SMEM>>>(
        xr, wqT, nullptr, nullptr, qh, ql, 8192, 3072, 1024);

    attn_flash_kernel<<<dim3(L_SEQ / 128, 16 * N_HEADS), 256, ATTN_SMEM>>>(rel_emb);

    gemm_tf32_kernel<<<dim3(1024 / BN, 8192 / BM), 256, GEMM_SMEM>>>(
        attn, woT, b_out, out, nullptr, nullptr, 8192, 1024, 1024);
}